// round 17
// baseline (speedup 1.0000x reference)
#include <cuda_runtime.h>
#include <math.h>

#define IMG_H 480
#define IMG_W 640
#define NB    4
#define PS    (IMG_H * IMG_W)

#define BTX   32
#define BTY   8
#define PXT   4                    // pixels per thread along x
#define TPW   (BTX * PXT)          // 128
#define TPH   BTY                  // 8
#define HALO  6
#define TILE_W 140                 // 128 + 12
#define TILE_H (TPH + 2 * HALO)    // 20

// float bit patterns of -2.0f / 0.0f / +2.0f live entirely in bits [31:30]
#define FB(o)  ((o) == -2 ? 0xC0000000u : ((o) == 2 ? 0x40000000u : 0u))
// pack (off_h, off_w) for candidate k: oh bits in [31:30], ow bits in [29:28]
#define PKC(k) (FB(2*((k)/3 - 1)) | (FB(2*((k)%3 - 1)) >> 2))

template<bool SAFE>
__device__ __forceinline__ void computeQ(
    const float (&tile)[TILE_H][TILE_W],
    int tx, int ty, int x0, int y,
    float* __restrict__ b0, float* __restrict__ b1, float* __restrict__ b2)
{
    // centers: tile row ty+6, cols 4tx+6..4tx+9 (8B-aligned -> 2 LDS.64)
    float cen[4];
    {
        const float2* cp = (const float2*)&tile[ty + 6][4 * tx + 6];
        float2 a = cp[0], b = cp[1];
        cen[0] = a.x; cen[1] = a.y; cen[2] = b.x; cen[3] = b.y;
    }

#pragma unroll
    for (int R = 0; R < 3; R++) {
        float    best[12];          // [C*4 + p]
        unsigned pk[12];
        float    buf[16];           // one 16-float row window (4 LDS.128)

        bool yok = true;
        if (!SAFE) yok = (unsigned)(y + 4 * (R - 1)) < (unsigned)IMG_H;

        // stream rows r = 0,1,2 of this group; k = 3r+c is row-major, so
        // ascending-r scan preserves jnp.argmin first-occurrence semantics
#pragma unroll
        for (int r = 0; r < 3; r++) {
            const float4* src = (const float4*)&tile[ty + 4 * R + 2 * r][4 * tx];
#pragma unroll
            for (int q = 0; q < 4; q++) {
                float4 v = src[q];
                buf[4 * q]     = v.x;
                buf[4 * q + 1] = v.y;
                buf[4 * q + 2] = v.z;
                buf[4 * q + 3] = v.w;
            }

#pragma unroll
            for (int C = 0; C < 3; C++) {
                const bool fullT = ((C == 1) == (R == 1));   // 9-cand taps
                const bool colT  = !fullT && (C == 1);       // k in {1,4,7}
                const bool rowT  = !fullT && (C != 1);       // k in {3,4,5}
#pragma unroll
                for (int c = 0; c < 3; c++) {
                    const bool active = fullT || (colT && c == 1) || (rowT && r == 1);
                    if (!active) continue;
                    const int  k       = 3 * r + c;
                    const bool isFirst = fullT ? (k == 0) : colT ? (k == 1) : (k == 3);
#pragma unroll
                    for (int p = 0; p < PXT; p++) {
                        const int q = C * 4 + p;
                        float v = buf[p + 4 * C + 2 * c] - cen[p];
                        if (isFirst) {
                            best[q] = v; pk[q] = PKC(k);
                        } else {
                            bool pr = fabsf(v) < fabsf(best[q]);  // strict <
                            best[q] = pr ? v : best[q];
                            pk[q]   = pr ? PKC(k) : pk[q];
                        }
                    }
                }
            }
        }

        // edge override + vectorized stores
#pragma unroll
        for (int C = 0; C < 3; C++) {
            const int j  = 3 * R + C;
            const int fk = ((C == 1) == (R == 1)) ? 0 : (C == 1 ? 1 : 3);
            if (!SAFE) {
#pragma unroll
                for (int p = 0; p < PXT; p++) {
                    // intermediate index OOB -> all allowed samples tie -> first k
                    bool xok = (unsigned)(x0 + p + 4 * (C - 1)) < (unsigned)IMG_W;
                    if (!(yok && xok)) pk[C * 4 + p] = PKC(fk);
                }
            }
            float4 hv = make_float4(
                __uint_as_float(pk[C * 4 + 0] & 0xC0000000u),
                __uint_as_float(pk[C * 4 + 1] & 0xC0000000u),
                __uint_as_float(pk[C * 4 + 2] & 0xC0000000u),
                __uint_as_float(pk[C * 4 + 3] & 0xC0000000u));
            float4 wv = make_float4(
                __uint_as_float((pk[C * 4 + 0] << 2) & 0xC0000000u),
                __uint_as_float((pk[C * 4 + 1] << 2) & 0xC0000000u),
                __uint_as_float((pk[C * 4 + 2] << 2) & 0xC0000000u),
                __uint_as_float((pk[C * 4 + 3] << 2) & 0xC0000000u));
            // 3 bases keep every store offset within STG immediate range
            const int jh = j, jw = j + 9;
            float* ph = (jh < 6) ? b0 + (size_t)jh * PS
                                 : (jh < 12) ? b1 + (size_t)(jh - 6) * PS
                                             : b2 + (size_t)(jh - 12) * PS;
            float* pw = (jw < 12) ? b1 + (size_t)(jw - 6) * PS
                                  : b2 + (size_t)(jw - 12) * PS;
            *(float4*)ph = hv;
            *(float4*)pw = wv;
        }
    }
}

__global__ void __launch_bounds__(BTX * BTY, 4)
DepthOffset_kernel(const float* __restrict__ depth, float* __restrict__ out)
{
    __shared__ __align__(16) float tile[TILE_H][TILE_W];

    const int b   = blockIdx.z;
    const int bx0 = blockIdx.x * TPW;
    const int by0 = blockIdx.y * TPH;
    const int tx  = threadIdx.x, ty = threadIdx.y;
    const int t   = ty * BTX + tx;

    const float* __restrict__ dp = depth + b * PS;

    // whole tile footprint (incl. halo) inside the image?
    const bool safe = (bx0 >= HALO) && (bx0 + TPW + HALO <= IMG_W) &&
                      (by0 >= HALO) && (by0 + TPH + HALO <= IMG_H);

    if (safe) {
        // float2 loader: gmem col bx0-6 is even -> 8B-aligned
        const int NF2 = TILE_H * (TILE_W / 2);          // 1400 float2
        for (int i = t; i < NF2; i += BTX * BTY) {
            int r  = i / (TILE_W / 2);
            int c2 = i - r * (TILE_W / 2);
            float2 v = *(const float2*)&dp[(by0 - HALO + r) * IMG_W + (bx0 - HALO) + 2 * c2];
            *(float2*)&tile[r][2 * c2] = v;
        }
    } else {
        for (int i = t; i < TILE_H * TILE_W; i += BTX * BTY) {
            int r  = i / TILE_W;
            int c  = i - r * TILE_W;
            int gy = by0 - HALO + r;
            int gx = bx0 - HALO + c;
            float v = 0.0f;
            if ((unsigned)gy < (unsigned)IMG_H && (unsigned)gx < (unsigned)IMG_W)
                v = dp[gy * IMG_W + gx];
            tile[r][c] = v;
        }
    }
    __syncthreads();

    const int x0 = bx0 + 4 * tx;
    const int y  = by0 + ty;
    float* __restrict__ base = out + (size_t)(b * 18) * PS + y * IMG_W + x0;
    float* __restrict__ bb1  = base + (size_t)6 * PS;
    float* __restrict__ bb2  = base + (size_t)12 * PS;

    if (safe)
        computeQ<true >(tile, tx, ty, x0, y, base, bb1, bb2);
    else
        computeQ<false>(tile, tx, ty, x0, y, base, bb1, bb2);
}

extern "C" void kernel_launch(void* const* d_in, const int* in_sizes, int n_in,
                              void* d_out, int out_size)
{
    const float* depth = (const float*)d_in[0];
    float* out = (float*)d_out;

    dim3 block(BTX, BTY);
    dim3 grid(IMG_W / TPW, IMG_H / TPH, NB);   // 5 x 60 x 4 = 1200
    DepthOffset_kernel<<<grid, block>>>(depth, out);
}